// round 12
// baseline (speedup 1.0000x reference)
#include <cuda_runtime.h>
#include <stdint.h>
#include <math.h>

#define HH 1280
#define WW 1920
#define BB 2
#define OH 427
#define OW 640
#define SENT2 0x7FFF7FFFu   // sentinel coords (32767,32767): loses to every real seed
#define RB 8                // rows per block, gmem JFA passes (grid.y = 160)
#define RBR 4               // rows per block, rowpair kernel  (grid.y = 320)

// Scratch (device globals: allocation-free rule)
__device__ float    g_depth[BB][HH * WW];          // 19.6 MB
__device__ uint32_t g_near[2][BB][HH * WW];        // 2 x 19.6 MB, ping-pong
__device__ float    g_full[BB][2][HH * WW];        // filled + dist, 39.3 MB

// ---------------------------------------------------------------------------
// XLA fused-emitter dot: separate multiplies, k-ascending adds, NO fma.
__device__ __forceinline__ float dot3_nofma(float a0, float a1, float a2,
                                            float b0, float b1, float b2) {
    float p0 = __fmul_rn(a0, b0);
    float p1 = __fmul_rn(a1, b1);
    float p2 = __fmul_rn(a2, b2);
    return __fadd_rn(__fadd_rn(p0, p1), p2);
}

// winner select, branch-free: packed |dr|,|dc| via vabsdiff2, exact int dist.
// ij = (i<<16)|j. Sentinel 0x7FFF7FFF -> dist ~1.9e9 (fits u32, > any real 5.3e6,
// sentinel-vs-sentinel equal -> strict '<' keeps cur). Matches reference BIG math.
__device__ __forceinline__ uint32_t jfa_better(uint32_t cur, uint32_t cand, uint32_t ij) {
    unsigned a = __vabsdiffs2(ij, cur);
    unsigned b = __vabsdiffs2(ij, cand);
    unsigned da = (a >> 16) * (a >> 16) + (a & 0xFFFFu) * (a & 0xFFFFu);
    unsigned db = (b >> 16) * (b >> 16) + (b & 0xFFFFu) * (b & 0xFFFFu);
    return (db < da) ? cand : cur;
}

__device__ __forceinline__ uint32_t seedv(int r, int c, float d) {
    return (d != 0.f) ? (uint32_t)((r << 16) | c) : SENT2;
}

// ---------------------------------------------------------------------------
// 1) zero depth canvas
__global__ void zero_depth_kernel(int nb) {
    int t = blockIdx.x * blockDim.x + threadIdx.x;
    int total = nb * HH * WW / 4;
    if (t < total) reinterpret_cast<float4*>(g_depth)[t] = make_float4(0.f, 0.f, 0.f, 0.f);
}

// ---------------------------------------------------------------------------
// 2) project points, scatter-add depth (duplicates sum, like reference)
__global__ void scatter_kernel(const float* __restrict__ pts,
                               const float* __restrict__ pose,
                               const float* __restrict__ ext,
                               const float* __restrict__ intr,
                               int N) {
    int idx = blockIdx.x * blockDim.x + threadIdx.x;
    int b = blockIdx.y;
    if (idx >= N) return;
    const float* p = pts + ((size_t)b * N + idx) * 3;
    float x = p[0], y = p[1], z = p[2];
    const float* P = pose + b * 16;
    const float* E = ext + b * 16;
    const float* K = intr + b * 9;
    float wx = __fadd_rn(dot3_nofma(x, y, z, P[0], P[1], P[2]),  P[3]);
    float wy = __fadd_rn(dot3_nofma(x, y, z, P[4], P[5], P[6]),  P[7]);
    float wz = __fadd_rn(dot3_nofma(x, y, z, P[8], P[9], P[10]), P[11]);
    float cx = __fadd_rn(dot3_nofma(wx, wy, wz, E[0], E[1], E[2]),  E[3]);
    float cy = __fadd_rn(dot3_nofma(wx, wy, wz, E[4], E[5], E[6]),  E[7]);
    float cz = __fadd_rn(dot3_nofma(wx, wy, wz, E[8], E[9], E[10]), E[11]);
    float pu = dot3_nofma(cx, cy, cz, K[0], K[1], K[2]);
    float pv = dot3_nofma(cx, cy, cz, K[3], K[4], K[5]);
    float pw = dot3_nofma(cx, cy, cz, K[6], K[7], K[8]);
    float u = __fdiv_rn(pu, pw);
    float v = __fdiv_rn(pv, pw);
    int r = (int)floorf(v);
    int c = (int)floorf(u);
    if (r >= 0 && r < HH && c >= 0 && c < WW) {
        float x2 = __fmul_rn(x, x);
        float y2 = __fmul_rn(y, y);
        float z2 = __fmul_rn(z, z);
        float d = __fsqrt_rn(__fadd_rn(__fadd_rn(x2, y2), z2));
        atomicAdd(&g_depth[b][r * WW + c], d);
    }
}

// ---------------------------------------------------------------------------
// 3a) fused A,B (d=+1) / F,G (d=-1) pair, aligned k (k % 4 == 0), RB rows/block.
//     A/F: cand(i,j) = S(r1, j+k)            r1 = i + d*k
//     B/G: cand(i,j) = postA(r1, j) = better_{(r1,j)}(S(r1,j), S(r2,j+k))
__global__ void __launch_bounds__(480) jfa_pair_a(int srcSel, int k, int d) {
    const int b = blockIdx.z;
    const int i0 = blockIdx.y * RB;
    const int j0 = threadIdx.x * 4;
    const uint32_t* __restrict__ s = g_near[srcSel][b];
    uint32_t* __restrict__ dst = g_near[srcSel ^ 1][b];
    const uint4 S4 = make_uint4(SENT2, SENT2, SENT2, SENT2);
    const bool okp = ((unsigned)(j0 + k) < (unsigned)WW);   // quad all-or-none
    const int dk = d * k;
#pragma unroll 2
    for (int r = 0; r < RB; r++) {
        const int i = i0 + r;
        const int r1 = i + dk, r2 = i + 2 * dk;
        const bool ok1 = ((unsigned)r1 < (unsigned)HH);
        const bool ok2 = ((unsigned)r2 < (unsigned)HH);
        uint4 cur = *reinterpret_cast<const uint4*>(s + i * WW + j0);
        uint4 R1p = S4, R1z = S4, R2p = S4;
        if (ok1) {
            const uint32_t* rp = s + r1 * WW;
            R1z = __ldg(reinterpret_cast<const uint4*>(rp + j0));
            if (okp) R1p = __ldg(reinterpret_cast<const uint4*>(rp + j0 + k));
        }
        if (ok2 && okp) R2p = __ldg(reinterpret_cast<const uint4*>(s + r2 * WW + j0 + k));
        const uint32_t ij0 = ((uint32_t)i  << 16) | (uint32_t)j0;
        const uint32_t ij1 = ((uint32_t)r1 << 16) | (uint32_t)j0; // garbage if r1 OOB: SENT-vs-SENT, harmless
        uint32_t curv[4] = {cur.x, cur.y, cur.z, cur.w};
        uint32_t r1p[4] = {R1p.x, R1p.y, R1p.z, R1p.w};
        uint32_t r1z[4] = {R1z.x, R1z.y, R1z.z, R1z.w};
        uint32_t r2p[4] = {R2p.x, R2p.y, R2p.z, R2p.w};
        uint32_t outv[4];
#pragma unroll
        for (int t = 0; t < 4; t++) {
            uint32_t a1 = jfa_better(curv[t], r1p[t], ij0 + t);   // post-A/F
            uint32_t a2 = jfa_better(r1z[t], r2p[t], ij1 + t);    // candB/G
            outv[t] = jfa_better(a1, a2, ij0 + t);                // post-B/G
        }
        *reinterpret_cast<uint4*>(dst + i * WW + j0) = make_uint4(outv[0], outv[1], outv[2], outv[3]);
    }
}

// ---------------------------------------------------------------------------
// 3b) fused pair for K in {1,2}: right-side 8-word windows, constexpr selects.
template <int K>
__global__ void __launch_bounds__(480) jfa_pair_s(int srcSel, int d) {
    const int b = blockIdx.z;
    const int i0 = blockIdx.y * RB;
    const int j0 = threadIdx.x * 4;
    const uint32_t* __restrict__ s = g_near[srcSel][b];
    uint32_t* __restrict__ dst = g_near[srcSel ^ 1][b];
    const uint4 S4 = make_uint4(SENT2, SENT2, SENT2, SENT2);
    const bool okr = (j0 + 7 < WW);
#pragma unroll 2
    for (int r = 0; r < RB; r++) {
        const int i = i0 + r;
        const int dk = d * K;
        const int r1 = i + dk, r2 = i + 2 * dk;
        const bool ok1 = ((unsigned)r1 < (unsigned)HH);
        const bool ok2 = ((unsigned)r2 < (unsigned)HH);
        uint4 cur = *reinterpret_cast<const uint4*>(s + i * WW + j0);
        uint4 B1 = S4, C1 = S4, B2 = S4, C2 = S4;
        if (ok1) {
            const uint32_t* rp = s + r1 * WW;
            B1 = __ldg(reinterpret_cast<const uint4*>(rp + j0));
            if (okr) C1 = __ldg(reinterpret_cast<const uint4*>(rp + j0 + 4));
        }
        if (ok2) {
            const uint32_t* rp = s + r2 * WW;
            B2 = __ldg(reinterpret_cast<const uint4*>(rp + j0));
            if (okr) C2 = __ldg(reinterpret_cast<const uint4*>(rp + j0 + 4));
        }
        uint32_t w1[8] = {B1.x, B1.y, B1.z, B1.w, C1.x, C1.y, C1.z, C1.w};
        uint32_t w2[8] = {B2.x, B2.y, B2.z, B2.w, C2.x, C2.y, C2.z, C2.w};
        const uint32_t ij0 = ((uint32_t)i  << 16) | (uint32_t)j0;
        const uint32_t ij1 = ((uint32_t)r1 << 16) | (uint32_t)j0;
        uint32_t curv[4] = {cur.x, cur.y, cur.z, cur.w};
        uint32_t outv[4];
#pragma unroll
        for (int t = 0; t < 4; t++) {
            uint32_t a1 = jfa_better(curv[t], w1[t + K], ij0 + t);
            uint32_t a2 = jfa_better(w1[t], w2[t + K], ij1 + t);
            outv[t] = jfa_better(a1, a2, ij0 + t);
        }
        *reinterpret_cast<uint4*>(dst + i * WW + j0) = make_uint4(outv[0], outv[1], outv[2], outv[3]);
    }
}

// ---------------------------------------------------------------------------
// 3c) very first JFA op: pair (A,B) of step k=1, seeds formed inline from
//     g_depth (replaces init_near). Writes g_near[0].
__global__ void __launch_bounds__(480) jfa_pair_init(int nb) {
    const int b = blockIdx.z;
    const int i0 = blockIdx.y * RB;
    const int j0 = threadIdx.x * 4;
    const float* __restrict__ dp = g_depth[b];
    uint32_t* __restrict__ dst = g_near[0][b];
    const bool okr = (j0 + 7 < WW);
#pragma unroll 2
    for (int r = 0; r < RB; r++) {
        const int i = i0 + r;
        const int r1 = i + 1, r2 = i + 2;
        const bool ok1 = (r1 < HH);
        const bool ok2 = (r2 < HH);
        float4 dC = *reinterpret_cast<const float4*>(dp + i * WW + j0);
        uint32_t curv[4] = { seedv(i, j0 + 0, dC.x), seedv(i, j0 + 1, dC.y),
                             seedv(i, j0 + 2, dC.z), seedv(i, j0 + 3, dC.w) };
        uint32_t w1[8], w2[8];
#pragma unroll
        for (int t = 0; t < 8; t++) { w1[t] = SENT2; w2[t] = SENT2; }
        if (ok1) {
            float4 a = __ldg(reinterpret_cast<const float4*>(dp + r1 * WW + j0));
            w1[0] = seedv(r1, j0 + 0, a.x); w1[1] = seedv(r1, j0 + 1, a.y);
            w1[2] = seedv(r1, j0 + 2, a.z); w1[3] = seedv(r1, j0 + 3, a.w);
            if (okr) {
                float4 c = __ldg(reinterpret_cast<const float4*>(dp + r1 * WW + j0 + 4));
                w1[4] = seedv(r1, j0 + 4, c.x); w1[5] = seedv(r1, j0 + 5, c.y);
                w1[6] = seedv(r1, j0 + 6, c.z); w1[7] = seedv(r1, j0 + 7, c.w);
            }
        }
        if (ok2) {
            float4 a = __ldg(reinterpret_cast<const float4*>(dp + r2 * WW + j0));
            w2[0] = seedv(r2, j0 + 0, a.x); w2[1] = seedv(r2, j0 + 1, a.y);
            w2[2] = seedv(r2, j0 + 2, a.z); w2[3] = seedv(r2, j0 + 3, a.w);
            if (okr) {
                float4 c = __ldg(reinterpret_cast<const float4*>(dp + r2 * WW + j0 + 4));
                w2[4] = seedv(r2, j0 + 4, c.x); w2[5] = seedv(r2, j0 + 5, c.y);
                w2[6] = seedv(r2, j0 + 6, c.z); w2[7] = seedv(r2, j0 + 7, c.w);
            }
        }
        const uint32_t ij0 = ((uint32_t)i  << 16) | (uint32_t)j0;
        const uint32_t ij1 = ((uint32_t)r1 << 16) | (uint32_t)j0;
        uint32_t outv[4];
#pragma unroll
        for (int t = 0; t < 4; t++) {
            uint32_t a1 = jfa_better(curv[t], w1[t + 1], ij0 + t);
            uint32_t a2 = jfa_better(w1[t], w2[t + 1], ij1 + t);
            outv[t] = jfa_better(a1, a2, ij0 + t);
        }
        *reinterpret_cast<uint4*>(dst + i * WW + j0) = make_uint4(outv[0], outv[1], outv[2], outv[3]);
    }
}

// ---------------------------------------------------------------------------
// 4a) single JFA pass (aligned dx: dx % 4 == 0), runtime dy/dx. For C, H.
__global__ void __launch_bounds__(480) jfa_pass_a(int srcSel, int dy, int dx) {
    const int b = blockIdx.z;
    const int i0 = blockIdx.y * RB;
    const int j0 = threadIdx.x * 4;
    const uint32_t* __restrict__ s = g_near[srcSel][b];
    uint32_t* __restrict__ dpt = g_near[srcSel ^ 1][b];
    const int jb = j0 - dx;
    const bool okc = ((unsigned)jb < (unsigned)WW);
#pragma unroll 2
    for (int r = 0; r < RB; r++) {
        const int i = i0 + r;
        const int si = i - dy;
        uint4 cur = *reinterpret_cast<const uint4*>(s + i * WW + j0);
        const bool ok = ((unsigned)si < (unsigned)HH) & okc;
        const uint4* p = reinterpret_cast<const uint4*>(s + (ok ? si * WW + jb : 0));
        uint4 n = __ldg(p);
        if (!ok) { n.x = SENT2; n.y = SENT2; n.z = SENT2; n.w = SENT2; }
        const uint32_t ijp = (uint32_t)((i << 16) | j0);
        uint32_t curv[4] = {cur.x, cur.y, cur.z, cur.w};
        uint32_t candv[4] = {n.x, n.y, n.z, n.w};
        uint32_t outv[4];
#pragma unroll
        for (int t = 0; t < 4; t++) outv[t] = jfa_better(curv[t], candv[t], ijp + t);
        *reinterpret_cast<uint4*>(dpt + i * WW + j0) = make_uint4(outv[0], outv[1], outv[2], outv[3]);
    }
}

// ---------------------------------------------------------------------------
// 4b) single pass, DX compile-time in {1,2} (cand col = j - DX), runtime dy.
template <int DX>
__global__ void __launch_bounds__(480) jfa_pass_s(int srcSel, int dy) {
    const int b = blockIdx.z;
    const int i0 = blockIdx.y * RB;
    const int j0 = threadIdx.x * 4;
    const uint32_t* __restrict__ s = g_near[srcSel][b];
    uint32_t* __restrict__ dpt = g_near[srcSel ^ 1][b];
    const int jb = j0 - DX;
    const int ws = jb & ~3;
    constexpr int off = (-DX) & 3;
    const bool okw = (ws >= 0 && ws + 7 < WW);
#pragma unroll 2
    for (int r = 0; r < RB; r++) {
        const int i = i0 + r;
        const int si = i - dy;
        uint4 cur = *reinterpret_cast<const uint4*>(s + i * WW + j0);
        uint32_t candv[4];
        if (((unsigned)si < (unsigned)HH) && okw) {
            const uint32_t* rp = s + si * WW;
            uint4 n0 = __ldg(reinterpret_cast<const uint4*>(rp + ws));
            uint4 n1 = __ldg(reinterpret_cast<const uint4*>(rp + ws + 4));
            uint32_t w[8] = {n0.x, n0.y, n0.z, n0.w, n1.x, n1.y, n1.z, n1.w};
#pragma unroll
            for (int t = 0; t < 4; t++) candv[t] = w[off + t];   // constexpr -> MOVs
        } else if ((unsigned)si < (unsigned)HH) {
#pragma unroll
            for (int t = 0; t < 4; t++) {
                int sj = jb + t;
                candv[t] = ((unsigned)sj < (unsigned)WW) ? __ldg(s + si * WW + sj) : SENT2;
            }
        } else {
            candv[0] = candv[1] = candv[2] = candv[3] = SENT2;
        }
        const uint32_t ijp = (uint32_t)((i << 16) | j0);
        uint32_t curv[4] = {cur.x, cur.y, cur.z, cur.w};
        uint32_t outv[4];
#pragma unroll
        for (int t = 0; t < 4; t++) outv[t] = jfa_better(curv[t], candv[t], ijp + t);
        *reinterpret_cast<uint4*>(dpt + i * WW + j0) = make_uint4(outv[0], outv[1], outv[2], outv[3]);
    }
}

// ---------------------------------------------------------------------------
// 4c) fused row-local pair: (0,-k) then (0,+k), sequential, exact, in place.
//     RBR rows per block, all held in smem.
__global__ void __launch_bounds__(480) jfa_rowpair_kernel(int srcSel, int k) {
    __shared__ uint32_t rows[RBR][WW];
    const int b = blockIdx.z;
    const int i0 = blockIdx.y * RBR;
    const int j0 = threadIdx.x * 4;
    uint32_t* __restrict__ base = g_near[srcSel][b];

    uint32_t curv[RBR][4];
#pragma unroll
    for (int r = 0; r < RBR; r++) {
        uint4 v = *reinterpret_cast<const uint4*>(base + (i0 + r) * WW + j0);
        *reinterpret_cast<uint4*>(&rows[r][j0]) = v;
        curv[r][0] = v.x; curv[r][1] = v.y; curv[r][2] = v.z; curv[r][3] = v.w;
    }
    __syncthreads();

    // direction (0,-k): cand = row[j + k]
    uint32_t nv[RBR][4];
#pragma unroll
    for (int r = 0; r < RBR; r++) {
        const uint32_t ijp = (uint32_t)(((i0 + r) << 16) | j0);
        int jb = j0 + k;
        uint32_t candv[4];
        if ((k & 3) == 0 && jb + 3 < WW) {
            uint4 n = *reinterpret_cast<const uint4*>(&rows[r][jb]);
            candv[0] = n.x; candv[1] = n.y; candv[2] = n.z; candv[3] = n.w;
        } else {
#pragma unroll
            for (int t = 0; t < 4; t++) candv[t] = (jb + t < WW) ? rows[r][jb + t] : SENT2;
        }
#pragma unroll
        for (int t = 0; t < 4; t++) nv[r][t] = jfa_better(curv[r][t], candv[t], ijp + t);
    }
    __syncthreads();           // all reads of stage-0 done
#pragma unroll
    for (int r = 0; r < RBR; r++)
        *reinterpret_cast<uint4*>(&rows[r][j0]) = make_uint4(nv[r][0], nv[r][1], nv[r][2], nv[r][3]);
    __syncthreads();           // stage-1 rows visible

    // direction (0,+k): cand = row[j - k]
#pragma unroll
    for (int r = 0; r < RBR; r++) {
        const uint32_t ijp = (uint32_t)(((i0 + r) << 16) | j0);
        int jb = j0 - k;
        uint32_t candv[4];
        if ((k & 3) == 0 && jb >= 0) {
            uint4 n = *reinterpret_cast<const uint4*>(&rows[r][jb]);
            candv[0] = n.x; candv[1] = n.y; candv[2] = n.z; candv[3] = n.w;
        } else {
#pragma unroll
            for (int t = 0; t < 4; t++) candv[t] = (jb + t >= 0) ? rows[r][jb + t] : SENT2;
        }
        uint32_t ov[4];
#pragma unroll
        for (int t = 0; t < 4; t++) ov[t] = jfa_better(nv[r][t], candv[t], ijp + t);
        *reinterpret_cast<uint4*>(base + (i0 + r) * WW + j0) = make_uint4(ov[0], ov[1], ov[2], ov[3]);
    }
}

// ---------------------------------------------------------------------------
// 5) filled depth + distance map
__global__ void fill_kernel(int nb, int finalSel) {
    int t = blockIdx.x * blockDim.x + threadIdx.x;
    int total = nb * HH * WW;
    if (t >= total) return;
    int b = t / (HH * WW);
    int pix = t % (HH * WW);
    int i = pix / WW;
    int j = pix % WW;
    float dep = g_depth[b][pix];
    uint32_t nn = g_near[finalSel][b][pix];
    int nr = (int)(nn >> 16);     if (nr > HH - 1) nr = HH - 1;
    int nc = (int)(nn & 0xFFFFu); if (nc > WW - 1) nc = WW - 1;
    bool valid = (dep != 0.f);
    float filled = valid ? dep : g_depth[b][nr * WW + nc];
    float dr = __fadd_rn((float)i, -(float)nr);
    float dc = __fadd_rn((float)j, -(float)nc);
    float dist = valid ? 0.f : __fsqrt_rn(__fadd_rn(__fmul_rn(dr, dr), __fmul_rn(dc, dc)));
    g_full[b][0][pix] = filled;
    g_full[b][1][pix] = dist;
}

// ---------------------------------------------------------------------------
// 6) jax.image.resize(method='linear', antialias=True): separable triangle,
//    fp32 weights exactly as jax computes them, fp32 accumulation.
__global__ void resize_kernel(float* __restrict__ out, int nb) {
    int t = blockIdx.x * blockDim.x + threadIdx.x;
    int total = nb * 2 * OH * OW;
    if (t >= total) return;
    int ox = t % OW;
    int oy = (t / OW) % OH;
    int ch = (t / (OW * OH)) % 2;
    int b  =  t / (OW * OH * 2);

    const double s_h = (double)OH / (double)HH;
    const double s_w = (double)OW / (double)WW;
    const float inv_h = (float)(1.0 / s_h);
    const float inv_w = (float)(1.0 / s_w);

    float sfy = __fadd_rn(__fmul_rn(__fadd_rn((float)oy, 0.5f), inv_h), -0.5f);
    float sfx = __fadd_rn(__fmul_rn(__fadd_rn((float)ox, 0.5f), inv_w), -0.5f);

    int y0 = (int)ceilf(sfy - inv_h) - 1;  if (y0 < 0) y0 = 0;
    int y1 = (int)floorf(sfy + inv_h) + 1; if (y1 > HH - 1) y1 = HH - 1;
    int x0 = (int)ceilf(sfx - inv_w) - 1;  if (x0 < 0) x0 = 0;
    int x1 = (int)floorf(sfx + inv_w) + 1; if (x1 > WW - 1) x1 = WW - 1;

    float wx[10];
    float wxs = 0.0f;
    int nx = x1 - x0 + 1;
    if (nx > 10) nx = 10;
    for (int k = 0; k < nx; k++) {
        float d = fabsf(__fadd_rn(sfx, -(float)(x0 + k)));
        float xx = __fdiv_rn(d, inv_w);
        float w = __fadd_rn(1.0f, -xx);
        if (w < 0.0f) w = 0.0f;
        wx[k] = w;
        wxs = __fadd_rn(wxs, w);
    }
    for (int k = 0; k < nx; k++) wx[k] = __fdiv_rn(wx[k], wxs);

    const float* __restrict__ src = g_full[b][ch];
    float acc = 0.0f;
    float wys = 0.0f;
    float wy[10];
    int ny = y1 - y0 + 1;
    if (ny > 10) ny = 10;
    for (int k = 0; k < ny; k++) {
        float d = fabsf(__fadd_rn(sfy, -(float)(y0 + k)));
        float xx = __fdiv_rn(d, inv_h);
        float w = __fadd_rn(1.0f, -xx);
        if (w < 0.0f) w = 0.0f;
        wy[k] = w;
        wys = __fadd_rn(wys, w);
    }
    for (int k = 0; k < ny; k++) {
        float wyn = __fdiv_rn(wy[k], wys);
        const float* row = src + (y0 + k) * WW;
        float rowacc = 0.0f;
        for (int m = 0; m < nx; m++) {
            rowacc = __fmaf_rn(wx[m], row[x0 + m], rowacc);
        }
        acc = __fmaf_rn(wyn, rowacc, acc);
    }
    out[(((size_t)b * 2 + ch) * OH + oy) * OW + ox] = acc;
}

// ---------------------------------------------------------------------------
extern "C" void kernel_launch(void* const* d_in, const int* in_sizes, int n_in,
                              void* d_out, int out_size) {
    const float* pts  = (const float*)d_in[0];  // (B,N,3)
    const float* pose = (const float*)d_in[1];  // (B,4,4)
    const float* ext  = (const float*)d_in[2];  // (B,4,4)
    const float* intr = (const float*)d_in[3];  // (B,3,3)

    int nb = in_sizes[1] / 16;
    if (nb < 1) nb = 1;
    if (nb > BB) nb = BB;
    int N = in_sizes[0] / (nb * 3);

    int totalPix = nb * HH * WW;

    zero_depth_kernel<<<(totalPix / 4 + 255) / 256, 256>>>(nb);

    dim3 sg((N + 255) / 256, nb);
    scatter_kernel<<<sg, 256>>>(pts, pose, ext, intr, N);

    dim3 jgP(1, HH / RB, nb);    // gmem JFA passes: 160 x nb blocks
    dim3 jgR(1, HH / RBR, nb);   // rowpair: 320 x nb blocks
    int src;

    // Per step (reference order): [A,B] pair, C=(-k,+k) single, [D,E] rowpair
    // (in place), [F,G] pair, H=(k,+k) single.

    // step k=1, FIRST: seeds formed inline from depth inside the A,B pair.
    jfa_pair_init<<<jgP, 480>>>(nb);            // state -> g_near[0]
    src = 0;
    jfa_pass_s<1><<<jgP, 480>>>(src, -1); src ^= 1;   // C
    jfa_rowpair_kernel<<<jgR, 480>>>(src, 1);          // D,E in place
    jfa_pair_s<1><<<jgP, 480>>>(src, -1); src ^= 1;   // F,G
    jfa_pass_s<1><<<jgP, 480>>>(src, 1);  src ^= 1;   // H

    auto stepA = [&](int k) {                  // k % 4 == 0
        jfa_pair_a<<<jgP, 480>>>(src, k, +1); src ^= 1;   // A,B
        jfa_pass_a<<<jgP, 480>>>(src, -k, k); src ^= 1;   // C
        jfa_rowpair_kernel<<<jgR, 480>>>(src, k);          // D,E
        jfa_pair_a<<<jgP, 480>>>(src, k, -1); src ^= 1;   // F,G
        jfa_pass_a<<<jgP, 480>>>(src, k, k);  src ^= 1;   // H
    };
    auto step1 = [&]() {
        jfa_pair_s<1><<<jgP, 480>>>(src, +1); src ^= 1;
        jfa_pass_s<1><<<jgP, 480>>>(src, -1); src ^= 1;
        jfa_rowpair_kernel<<<jgR, 480>>>(src, 1);
        jfa_pair_s<1><<<jgP, 480>>>(src, -1); src ^= 1;
        jfa_pass_s<1><<<jgP, 480>>>(src, 1);  src ^= 1;
    };
    auto step2 = [&]() {
        jfa_pair_s<2><<<jgP, 480>>>(src, +1); src ^= 1;
        jfa_pass_s<2><<<jgP, 480>>>(src, -2); src ^= 1;
        jfa_rowpair_kernel<<<jgR, 480>>>(src, 2);
        jfa_pair_s<2><<<jgP, 480>>>(src, -1); src ^= 1;
        jfa_pass_s<2><<<jgP, 480>>>(src, 2);  src ^= 1;
    };

    // schedule: 1 (done), 1024, 512, 256, 128, 64, 32, 16, 8, 4, 2, 1
    stepA(1024);
    stepA(512);
    stepA(256);
    stepA(128);
    stepA(64);
    stepA(32);
    stepA(16);
    stepA(8);
    stepA(4);
    step2();
    step1();

    fill_kernel<<<(totalPix + 255) / 256, 256>>>(nb, src);

    int outTotal = nb * 2 * OH * OW;
    resize_kernel<<<(outTotal + 255) / 256, 256>>>((float*)d_out, nb);
}

// round 13
// speedup vs baseline: 1.3890x; 1.3890x over previous
#include <cuda_runtime.h>
#include <stdint.h>
#include <math.h>

#define HH 1280
#define WW 1920
#define BB 2
#define OH 427
#define OW 640
#define SENT2 0x7FFF7FFFu   // sentinel coords (32767,32767): loses to every real seed

// Scratch (device globals: allocation-free rule)
__device__ float    g_depth[BB][HH * WW];          // 19.6 MB
__device__ uint32_t g_near[2][BB][HH * WW];        // 2 x 19.6 MB, ping-pong
__device__ float    g_full[BB][2][HH * WW];        // filled + dist, 39.3 MB

// ---------------------------------------------------------------------------
// XLA fused-emitter dot: separate multiplies, k-ascending adds, NO fma.
__device__ __forceinline__ float dot3_nofma(float a0, float a1, float a2,
                                            float b0, float b1, float b2) {
    float p0 = __fmul_rn(a0, b0);
    float p1 = __fmul_rn(a1, b1);
    float p2 = __fmul_rn(a2, b2);
    return __fadd_rn(__fadd_rn(p0, p1), p2);
}

// winner select, branch-free: packed |dr|,|dc| via vabsdiff2, exact int dist.
// ij = (i<<16)|j. Sentinel 0x7FFF7FFF -> dist ~1.9e9 (fits u32, > any real 5.3e6,
// sentinel-vs-sentinel equal -> strict '<' keeps cur). Matches reference BIG math.
__device__ __forceinline__ uint32_t jfa_better(uint32_t cur, uint32_t cand, uint32_t ij) {
    unsigned a = __vabsdiffs2(ij, cur);
    unsigned b = __vabsdiffs2(ij, cand);
    unsigned da = (a >> 16) * (a >> 16) + (a & 0xFFFFu) * (a & 0xFFFFu);
    unsigned db = (b >> 16) * (b >> 16) + (b & 0xFFFFu) * (b & 0xFFFFu);
    return (db < da) ? cand : cur;
}

__device__ __forceinline__ uint32_t seedv(int r, int c, float d) {
    return (d != 0.f) ? (uint32_t)((r << 16) | c) : SENT2;
}

// ---------------------------------------------------------------------------
// 1) zero depth canvas
__global__ void zero_depth_kernel(int nb) {
    int t = blockIdx.x * blockDim.x + threadIdx.x;
    int total = nb * HH * WW / 4;
    if (t < total) reinterpret_cast<float4*>(g_depth)[t] = make_float4(0.f, 0.f, 0.f, 0.f);
}

// ---------------------------------------------------------------------------
// 2) project points, scatter-add depth (duplicates sum, like reference)
__global__ void scatter_kernel(const float* __restrict__ pts,
                               const float* __restrict__ pose,
                               const float* __restrict__ ext,
                               const float* __restrict__ intr,
                               int N) {
    int idx = blockIdx.x * blockDim.x + threadIdx.x;
    int b = blockIdx.y;
    if (idx >= N) return;
    const float* p = pts + ((size_t)b * N + idx) * 3;
    float x = p[0], y = p[1], z = p[2];
    const float* P = pose + b * 16;
    const float* E = ext + b * 16;
    const float* K = intr + b * 9;
    float wx = __fadd_rn(dot3_nofma(x, y, z, P[0], P[1], P[2]),  P[3]);
    float wy = __fadd_rn(dot3_nofma(x, y, z, P[4], P[5], P[6]),  P[7]);
    float wz = __fadd_rn(dot3_nofma(x, y, z, P[8], P[9], P[10]), P[11]);
    float cx = __fadd_rn(dot3_nofma(wx, wy, wz, E[0], E[1], E[2]),  E[3]);
    float cy = __fadd_rn(dot3_nofma(wx, wy, wz, E[4], E[5], E[6]),  E[7]);
    float cz = __fadd_rn(dot3_nofma(wx, wy, wz, E[8], E[9], E[10]), E[11]);
    float pu = dot3_nofma(cx, cy, cz, K[0], K[1], K[2]);
    float pv = dot3_nofma(cx, cy, cz, K[3], K[4], K[5]);
    float pw = dot3_nofma(cx, cy, cz, K[6], K[7], K[8]);
    float u = __fdiv_rn(pu, pw);
    float v = __fdiv_rn(pv, pw);
    int r = (int)floorf(v);
    int c = (int)floorf(u);
    if (r >= 0 && r < HH && c >= 0 && c < WW) {
        float x2 = __fmul_rn(x, x);
        float y2 = __fmul_rn(y, y);
        float z2 = __fmul_rn(z, z);
        float d = __fsqrt_rn(__fadd_rn(__fadd_rn(x2, y2), z2));
        atomicAdd(&g_depth[b][r * WW + c], d);
    }
}

// ---------------------------------------------------------------------------
// 3a) fused A,B (d=+1) / F,G (d=-1) pair, aligned k (k % 4 == 0).
//     A/F: cand(i,j) = S(r1, j+k)            r1 = i + d*k
//     B/G: cand(i,j) = postA(r1, j) = better_{(r1,j)}(S(r1,j), S(r2,j+k))
//     (exact recomputation of the sequential two passes; r2 = i + 2*d*k)
__global__ void __launch_bounds__(480) jfa_pair_a(int srcSel, int k, int d) {
    const int b = blockIdx.z;
    const int i = blockIdx.y;
    const int j0 = threadIdx.x * 4;
    const uint32_t* __restrict__ s = g_near[srcSel][b];
    uint32_t* __restrict__ dst = g_near[srcSel ^ 1][b];
    const uint4 S4 = make_uint4(SENT2, SENT2, SENT2, SENT2);

    uint4 cur = *reinterpret_cast<const uint4*>(s + i * WW + j0);
    const int dk = d * k;
    const int r1 = i + dk, r2 = i + 2 * dk;
    const bool ok1 = ((unsigned)r1 < (unsigned)HH);
    const bool ok2 = ((unsigned)r2 < (unsigned)HH);
    const bool okp = ((unsigned)(j0 + k) < (unsigned)WW);   // quad all-or-none

    uint4 R1p = S4, R1z = S4, R2p = S4;
    if (ok1) {
        const uint32_t* r = s + r1 * WW;
        R1z = __ldg(reinterpret_cast<const uint4*>(r + j0));
        if (okp) R1p = __ldg(reinterpret_cast<const uint4*>(r + j0 + k));
    }
    if (ok2 && okp) R2p = __ldg(reinterpret_cast<const uint4*>(s + r2 * WW + j0 + k));

    const uint32_t ij0 = ((uint32_t)i  << 16) | (uint32_t)j0;
    const uint32_t ij1 = ((uint32_t)r1 << 16) | (uint32_t)j0;   // garbage if r1 OOB: SENT-vs-SENT, harmless
    uint32_t curv[4] = {cur.x, cur.y, cur.z, cur.w};
    uint32_t r1p[4] = {R1p.x, R1p.y, R1p.z, R1p.w};
    uint32_t r1z[4] = {R1z.x, R1z.y, R1z.z, R1z.w};
    uint32_t r2p[4] = {R2p.x, R2p.y, R2p.z, R2p.w};
    uint32_t outv[4];
#pragma unroll
    for (int t = 0; t < 4; t++) {
        uint32_t a1 = jfa_better(curv[t], r1p[t], ij0 + t);   // post-A/F
        uint32_t a2 = jfa_better(r1z[t], r2p[t], ij1 + t);    // candB/G
        outv[t] = jfa_better(a1, a2, ij0 + t);                // post-B/G
    }
    *reinterpret_cast<uint4*>(dst + i * WW + j0) = make_uint4(outv[0], outv[1], outv[2], outv[3]);
}

// ---------------------------------------------------------------------------
// 3b) fused pair for K in {1,2}: right-side 8-word windows, constexpr selects.
template <int K>
__global__ void __launch_bounds__(480) jfa_pair_s(int srcSel, int d) {
    const int b = blockIdx.z;
    const int i = blockIdx.y;
    const int j0 = threadIdx.x * 4;
    const uint32_t* __restrict__ s = g_near[srcSel][b];
    uint32_t* __restrict__ dst = g_near[srcSel ^ 1][b];
    const uint4 S4 = make_uint4(SENT2, SENT2, SENT2, SENT2);

    uint4 cur = *reinterpret_cast<const uint4*>(s + i * WW + j0);
    const int dk = d * K;
    const int r1 = i + dk, r2 = i + 2 * dk;
    const bool ok1 = ((unsigned)r1 < (unsigned)HH);
    const bool ok2 = ((unsigned)r2 < (unsigned)HH);
    const bool okr = (j0 + 7 < WW);

    uint4 B1 = S4, C1 = S4, B2 = S4, C2 = S4;
    if (ok1) {
        const uint32_t* r = s + r1 * WW;
        B1 = __ldg(reinterpret_cast<const uint4*>(r + j0));
        if (okr) C1 = __ldg(reinterpret_cast<const uint4*>(r + j0 + 4));
    }
    if (ok2) {
        const uint32_t* r = s + r2 * WW;
        B2 = __ldg(reinterpret_cast<const uint4*>(r + j0));
        if (okr) C2 = __ldg(reinterpret_cast<const uint4*>(r + j0 + 4));
    }
    uint32_t w1[8] = {B1.x, B1.y, B1.z, B1.w, C1.x, C1.y, C1.z, C1.w};
    uint32_t w2[8] = {B2.x, B2.y, B2.z, B2.w, C2.x, C2.y, C2.z, C2.w};

    const uint32_t ij0 = ((uint32_t)i  << 16) | (uint32_t)j0;
    const uint32_t ij1 = ((uint32_t)r1 << 16) | (uint32_t)j0;
    uint32_t curv[4] = {cur.x, cur.y, cur.z, cur.w};
    uint32_t outv[4];
#pragma unroll
    for (int t = 0; t < 4; t++) {
        uint32_t a1 = jfa_better(curv[t], w1[t + K], ij0 + t);
        uint32_t a2 = jfa_better(w1[t], w2[t + K], ij1 + t);
        outv[t] = jfa_better(a1, a2, ij0 + t);
    }
    *reinterpret_cast<uint4*>(dst + i * WW + j0) = make_uint4(outv[0], outv[1], outv[2], outv[3]);
}

// ---------------------------------------------------------------------------
// 3c) very first JFA op: pair (A,B) of step k=1, seeds formed inline from
//     g_depth (replaces init_near). Writes g_near[0].
__global__ void __launch_bounds__(480) jfa_pair_init(int nb) {
    const int b = blockIdx.z;
    const int i = blockIdx.y;
    const int j0 = threadIdx.x * 4;
    const float* __restrict__ dp = g_depth[b];
    uint32_t* __restrict__ dst = g_near[0][b];

    const int r1 = i + 1, r2 = i + 2;
    const bool ok1 = (r1 < HH);
    const bool ok2 = (r2 < HH);
    const bool okr = (j0 + 7 < WW);

    float4 dC = *reinterpret_cast<const float4*>(dp + i * WW + j0);
    uint32_t curv[4] = { seedv(i, j0 + 0, dC.x), seedv(i, j0 + 1, dC.y),
                         seedv(i, j0 + 2, dC.z), seedv(i, j0 + 3, dC.w) };

    uint32_t w1[8], w2[8];
#pragma unroll
    for (int t = 0; t < 8; t++) { w1[t] = SENT2; w2[t] = SENT2; }
    if (ok1) {
        float4 a = __ldg(reinterpret_cast<const float4*>(dp + r1 * WW + j0));
        w1[0] = seedv(r1, j0 + 0, a.x); w1[1] = seedv(r1, j0 + 1, a.y);
        w1[2] = seedv(r1, j0 + 2, a.z); w1[3] = seedv(r1, j0 + 3, a.w);
        if (okr) {
            float4 c = __ldg(reinterpret_cast<const float4*>(dp + r1 * WW + j0 + 4));
            w1[4] = seedv(r1, j0 + 4, c.x); w1[5] = seedv(r1, j0 + 5, c.y);
            w1[6] = seedv(r1, j0 + 6, c.z); w1[7] = seedv(r1, j0 + 7, c.w);
        }
    }
    if (ok2) {
        float4 a = __ldg(reinterpret_cast<const float4*>(dp + r2 * WW + j0));
        w2[0] = seedv(r2, j0 + 0, a.x); w2[1] = seedv(r2, j0 + 1, a.y);
        w2[2] = seedv(r2, j0 + 2, a.z); w2[3] = seedv(r2, j0 + 3, a.w);
        if (okr) {
            float4 c = __ldg(reinterpret_cast<const float4*>(dp + r2 * WW + j0 + 4));
            w2[4] = seedv(r2, j0 + 4, c.x); w2[5] = seedv(r2, j0 + 5, c.y);
            w2[6] = seedv(r2, j0 + 6, c.z); w2[7] = seedv(r2, j0 + 7, c.w);
        }
    }

    const uint32_t ij0 = ((uint32_t)i  << 16) | (uint32_t)j0;
    const uint32_t ij1 = ((uint32_t)r1 << 16) | (uint32_t)j0;
    uint32_t outv[4];
#pragma unroll
    for (int t = 0; t < 4; t++) {
        uint32_t a1 = jfa_better(curv[t], w1[t + 1], ij0 + t);
        uint32_t a2 = jfa_better(w1[t], w2[t + 1], ij1 + t);
        outv[t] = jfa_better(a1, a2, ij0 + t);
    }
    *reinterpret_cast<uint4*>(dst + i * WW + j0) = make_uint4(outv[0], outv[1], outv[2], outv[3]);
}

// ---------------------------------------------------------------------------
// 4) fused C,D,E: directions (-k,+k), (0,-k), (0,+k), sequential & exact.
//    C reads pre-C rows i and i+k from gmem (true Jacobi); D,E are row-local
//    on the post-C row held in smem. Reads src, writes dst (one flip).
__global__ void __launch_bounds__(480) jfa_cde_kernel(int srcSel, int k) {
    __shared__ uint32_t row[WW];
    const int b = blockIdx.z;
    const int i = blockIdx.y;
    const int j0 = threadIdx.x * 4;
    const uint32_t* __restrict__ src = g_near[srcSel][b];
    uint32_t* __restrict__ dst = g_near[srcSel ^ 1][b];
    uint4 v = *reinterpret_cast<const uint4*>(src + i * WW + j0);
    uint32_t cur[4] = {v.x, v.y, v.z, v.w};
    const uint32_t ijp = (uint32_t)((i << 16) | j0);

    // C = (-k, +k): cand(i,j) = src(i+k, j-k)
    uint32_t cC[4];
    {
        const int si = i + k;
        const int jb = j0 - k;
        if ((unsigned)si < (unsigned)HH) {
            const uint32_t* rp = src + si * WW;
            if ((k & 3) == 0) {   // aligned: all-or-none window
                const bool ok = ((unsigned)jb < (unsigned)WW);
                uint4 n = __ldg(reinterpret_cast<const uint4*>(rp + (ok ? jb : 0)));
                if (!ok) { n.x = SENT2; n.y = SENT2; n.z = SENT2; n.w = SENT2; }
                cC[0] = n.x; cC[1] = n.y; cC[2] = n.z; cC[3] = n.w;
            } else {
#pragma unroll
                for (int t = 0; t < 4; t++) {
                    int sj = jb + t;
                    cC[t] = ((unsigned)sj < (unsigned)WW) ? __ldg(rp + sj) : SENT2;
                }
            }
        } else {
            cC[0] = cC[1] = cC[2] = cC[3] = SENT2;
        }
    }
    uint32_t v0[4];
#pragma unroll
    for (int t = 0; t < 4; t++) v0[t] = jfa_better(cur[t], cC[t], ijp + t);
    *reinterpret_cast<uint4*>(row + j0) = make_uint4(v0[0], v0[1], v0[2], v0[3]);
    __syncthreads();

    // D = (0, -k): cand = row[j + k]   (post-C)
    uint32_t v1[4];
    {
        const int jd = j0 + k;
        uint32_t cD[4];
        if ((k & 3) == 0 && jd + 3 < WW) {
            uint4 n = *reinterpret_cast<const uint4*>(row + jd);
            cD[0] = n.x; cD[1] = n.y; cD[2] = n.z; cD[3] = n.w;
        } else {
#pragma unroll
            for (int t = 0; t < 4; t++) cD[t] = (jd + t < WW) ? row[jd + t] : SENT2;
        }
#pragma unroll
        for (int t = 0; t < 4; t++) v1[t] = jfa_better(v0[t], cD[t], ijp + t);
    }
    __syncthreads();        // all D reads of post-C row done
    *reinterpret_cast<uint4*>(row + j0) = make_uint4(v1[0], v1[1], v1[2], v1[3]);
    __syncthreads();        // post-D row visible

    // E = (0, +k): cand = row[j - k]   (post-D)
    uint32_t outv[4];
    {
        const int je = j0 - k;
        uint32_t cE[4];
        if ((k & 3) == 0 && je >= 0) {
            uint4 n = *reinterpret_cast<const uint4*>(row + je);
            cE[0] = n.x; cE[1] = n.y; cE[2] = n.z; cE[3] = n.w;
        } else {
#pragma unroll
            for (int t = 0; t < 4; t++) cE[t] = (je + t >= 0) ? row[je + t] : SENT2;
        }
#pragma unroll
        for (int t = 0; t < 4; t++) outv[t] = jfa_better(v1[t], cE[t], ijp + t);
    }
    *reinterpret_cast<uint4*>(dst + i * WW + j0) = make_uint4(outv[0], outv[1], outv[2], outv[3]);
}

// ---------------------------------------------------------------------------
// 5a) single JFA pass (aligned dx: dx % 4 == 0), runtime dy/dx. For H.
__global__ void __launch_bounds__(480) jfa_pass_a(int srcSel, int dy, int dx) {
    const int b = blockIdx.z;
    const int i = blockIdx.y;
    const int j0 = threadIdx.x * 4;
    const uint32_t* __restrict__ s = g_near[srcSel][b];
    uint32_t* __restrict__ dpt = g_near[srcSel ^ 1][b];
    uint4 cur = *reinterpret_cast<const uint4*>(s + i * WW + j0);
    const int si = i - dy;
    const int jb = j0 - dx;
    const bool ok = ((unsigned)si < (unsigned)HH) & ((unsigned)jb < (unsigned)WW);
    const uint4* p = reinterpret_cast<const uint4*>(s + (ok ? si * WW + jb : 0));
    uint4 n = __ldg(p);
    if (!ok) { n.x = SENT2; n.y = SENT2; n.z = SENT2; n.w = SENT2; }
    const uint32_t ijp = (uint32_t)((i << 16) | j0);
    uint32_t curv[4] = {cur.x, cur.y, cur.z, cur.w};
    uint32_t candv[4] = {n.x, n.y, n.z, n.w};
    uint32_t outv[4];
#pragma unroll
    for (int t = 0; t < 4; t++) outv[t] = jfa_better(curv[t], candv[t], ijp + t);
    *reinterpret_cast<uint4*>(dpt + i * WW + j0) = make_uint4(outv[0], outv[1], outv[2], outv[3]);
}

// ---------------------------------------------------------------------------
// 5b) single pass, DX compile-time in {1,2} (cand col = j - DX), runtime dy.
template <int DX>
__global__ void __launch_bounds__(480) jfa_pass_s(int srcSel, int dy) {
    const int b = blockIdx.z;
    const int i = blockIdx.y;
    const int j0 = threadIdx.x * 4;
    const uint32_t* __restrict__ s = g_near[srcSel][b];
    uint32_t* __restrict__ dpt = g_near[srcSel ^ 1][b];
    uint4 cur = *reinterpret_cast<const uint4*>(s + i * WW + j0);
    const int si = i - dy;
    const int jb = j0 - DX;
    const int ws = jb & ~3;
    constexpr int off = (-DX) & 3;
    uint32_t candv[4];
    if (((unsigned)si < (unsigned)HH) && ws >= 0 && ws + 7 < WW) {
        const uint32_t* rp = s + si * WW;
        uint4 n0 = __ldg(reinterpret_cast<const uint4*>(rp + ws));
        uint4 n1 = __ldg(reinterpret_cast<const uint4*>(rp + ws + 4));
        uint32_t w[8] = {n0.x, n0.y, n0.z, n0.w, n1.x, n1.y, n1.z, n1.w};
#pragma unroll
        for (int t = 0; t < 4; t++) candv[t] = w[off + t];   // constexpr -> MOVs
    } else if ((unsigned)si < (unsigned)HH) {
#pragma unroll
        for (int t = 0; t < 4; t++) {
            int sj = jb + t;
            candv[t] = ((unsigned)sj < (unsigned)WW) ? __ldg(s + si * WW + sj) : SENT2;
        }
    } else {
        candv[0] = candv[1] = candv[2] = candv[3] = SENT2;
    }
    const uint32_t ijp = (uint32_t)((i << 16) | j0);
    uint32_t curv[4] = {cur.x, cur.y, cur.z, cur.w};
    uint32_t outv[4];
#pragma unroll
    for (int t = 0; t < 4; t++) outv[t] = jfa_better(curv[t], candv[t], ijp + t);
    *reinterpret_cast<uint4*>(dpt + i * WW + j0) = make_uint4(outv[0], outv[1], outv[2], outv[3]);
}

// ---------------------------------------------------------------------------
// 6) filled depth + distance map
__global__ void fill_kernel(int nb, int finalSel) {
    int t = blockIdx.x * blockDim.x + threadIdx.x;
    int total = nb * HH * WW;
    if (t >= total) return;
    int b = t / (HH * WW);
    int pix = t % (HH * WW);
    int i = pix / WW;
    int j = pix % WW;
    float dep = g_depth[b][pix];
    uint32_t nn = g_near[finalSel][b][pix];
    int nr = (int)(nn >> 16);     if (nr > HH - 1) nr = HH - 1;
    int nc = (int)(nn & 0xFFFFu); if (nc > WW - 1) nc = WW - 1;
    bool valid = (dep != 0.f);
    float filled = valid ? dep : g_depth[b][nr * WW + nc];
    float dr = __fadd_rn((float)i, -(float)nr);
    float dc = __fadd_rn((float)j, -(float)nc);
    float dist = valid ? 0.f : __fsqrt_rn(__fadd_rn(__fmul_rn(dr, dr), __fmul_rn(dc, dc)));
    g_full[b][0][pix] = filled;
    g_full[b][1][pix] = dist;
}

// ---------------------------------------------------------------------------
// 7) jax.image.resize(method='linear', antialias=True): separable triangle,
//    fp32 weights exactly as jax computes them, fp32 accumulation.
__global__ void resize_kernel(float* __restrict__ out, int nb) {
    int t = blockIdx.x * blockDim.x + threadIdx.x;
    int total = nb * 2 * OH * OW;
    if (t >= total) return;
    int ox = t % OW;
    int oy = (t / OW) % OH;
    int ch = (t / (OW * OH)) % 2;
    int b  =  t / (OW * OH * 2);

    const double s_h = (double)OH / (double)HH;
    const double s_w = (double)OW / (double)WW;
    const float inv_h = (float)(1.0 / s_h);
    const float inv_w = (float)(1.0 / s_w);

    float sfy = __fadd_rn(__fmul_rn(__fadd_rn((float)oy, 0.5f), inv_h), -0.5f);
    float sfx = __fadd_rn(__fmul_rn(__fadd_rn((float)ox, 0.5f), inv_w), -0.5f);

    int y0 = (int)ceilf(sfy - inv_h) - 1;  if (y0 < 0) y0 = 0;
    int y1 = (int)floorf(sfy + inv_h) + 1; if (y1 > HH - 1) y1 = HH - 1;
    int x0 = (int)ceilf(sfx - inv_w) - 1;  if (x0 < 0) x0 = 0;
    int x1 = (int)floorf(sfx + inv_w) + 1; if (x1 > WW - 1) x1 = WW - 1;

    float wx[10];
    float wxs = 0.0f;
    int nx = x1 - x0 + 1;
    if (nx > 10) nx = 10;
    for (int k = 0; k < nx; k++) {
        float d = fabsf(__fadd_rn(sfx, -(float)(x0 + k)));
        float xx = __fdiv_rn(d, inv_w);
        float w = __fadd_rn(1.0f, -xx);
        if (w < 0.0f) w = 0.0f;
        wx[k] = w;
        wxs = __fadd_rn(wxs, w);
    }
    for (int k = 0; k < nx; k++) wx[k] = __fdiv_rn(wx[k], wxs);

    const float* __restrict__ src = g_full[b][ch];
    float acc = 0.0f;
    float wys = 0.0f;
    float wy[10];
    int ny = y1 - y0 + 1;
    if (ny > 10) ny = 10;
    for (int k = 0; k < ny; k++) {
        float d = fabsf(__fadd_rn(sfy, -(float)(y0 + k)));
        float xx = __fdiv_rn(d, inv_h);
        float w = __fadd_rn(1.0f, -xx);
        if (w < 0.0f) w = 0.0f;
        wy[k] = w;
        wys = __fadd_rn(wys, w);
    }
    for (int k = 0; k < ny; k++) {
        float wyn = __fdiv_rn(wy[k], wys);
        const float* row = src + (y0 + k) * WW;
        float rowacc = 0.0f;
        for (int m = 0; m < nx; m++) {
            rowacc = __fmaf_rn(wx[m], row[x0 + m], rowacc);
        }
        acc = __fmaf_rn(wyn, rowacc, acc);
    }
    out[(((size_t)b * 2 + ch) * OH + oy) * OW + ox] = acc;
}

// ---------------------------------------------------------------------------
extern "C" void kernel_launch(void* const* d_in, const int* in_sizes, int n_in,
                              void* d_out, int out_size) {
    const float* pts  = (const float*)d_in[0];  // (B,N,3)
    const float* pose = (const float*)d_in[1];  // (B,4,4)
    const float* ext  = (const float*)d_in[2];  // (B,4,4)
    const float* intr = (const float*)d_in[3];  // (B,3,3)

    int nb = in_sizes[1] / 16;
    if (nb < 1) nb = 1;
    if (nb > BB) nb = BB;
    int N = in_sizes[0] / (nb * 3);

    int totalPix = nb * HH * WW;

    zero_depth_kernel<<<(totalPix / 4 + 255) / 256, 256>>>(nb);

    dim3 sg((N + 255) / 256, nb);
    scatter_kernel<<<sg, 256>>>(pts, pose, ext, intr, N);

    dim3 jg(1, HH, nb);
    int src;

    // Per step (reference order): [A,B] pair, [C,D,E] fused (C gmem Jacobi +
    // D,E smem row-local), [F,G] pair, H single. 4 launches / step.

    // step k=1, FIRST: seeds formed inline from depth inside the A,B pair.
    jfa_pair_init<<<jg, 480>>>(nb);                  // state -> g_near[0]
    src = 0;
    jfa_cde_kernel<<<jg, 480>>>(src, 1); src ^= 1;   // C,D,E
    jfa_pair_s<1><<<jg, 480>>>(src, -1); src ^= 1;   // F,G
    jfa_pass_s<1><<<jg, 480>>>(src, 1);  src ^= 1;   // H

    auto stepA = [&](int k) {                        // k % 4 == 0
        jfa_pair_a<<<jg, 480>>>(src, k, +1); src ^= 1;   // A,B
        jfa_cde_kernel<<<jg, 480>>>(src, k); src ^= 1;   // C,D,E
        jfa_pair_a<<<jg, 480>>>(src, k, -1); src ^= 1;   // F,G
        jfa_pass_a<<<jg, 480>>>(src, k, k);  src ^= 1;   // H
    };
    auto step1 = [&]() {
        jfa_pair_s<1><<<jg, 480>>>(src, +1); src ^= 1;
        jfa_cde_kernel<<<jg, 480>>>(src, 1); src ^= 1;
        jfa_pair_s<1><<<jg, 480>>>(src, -1); src ^= 1;
        jfa_pass_s<1><<<jg, 480>>>(src, 1);  src ^= 1;
    };
    auto step2 = [&]() {
        jfa_pair_s<2><<<jg, 480>>>(src, +1); src ^= 1;
        jfa_cde_kernel<<<jg, 480>>>(src, 2); src ^= 1;
        jfa_pair_s<2><<<jg, 480>>>(src, -1); src ^= 1;
        jfa_pass_s<2><<<jg, 480>>>(src, 2);  src ^= 1;
    };

    // schedule: 1 (done), 1024, 512, 256, 128, 64, 32, 16, 8, 4, 2, 1
    stepA(1024);
    stepA(512);
    stepA(256);
    stepA(128);
    stepA(64);
    stepA(32);
    stepA(16);
    stepA(8);
    stepA(4);
    step2();
    step1();

    fill_kernel<<<(totalPix + 255) / 256, 256>>>(nb, src);

    int outTotal = nb * 2 * OH * OW;
    resize_kernel<<<(outTotal + 255) / 256, 256>>>((float*)d_out, nb);
}